// round 12
// baseline (speedup 1.0000x reference)
#include <cuda_runtime.h>
#include <math.h>
#include <cstdint>

#define NB 32768
#define ND 128
#define NH 512
#define NE 16
#define CHUNK 64
#define NCHUNKS (NH / CHUNK)
#define NSTAGES (NCHUNKS * 2)   // 16: G1/G2 alternating
#define MAX_TILES 320
#define NBLOCKS 256             // persistent work-stealing blocks
#define NTHREADS 512            // 16 warps: 4(m) x 4(n)

// strides in words (floats), chosen for conflict-free frag access
#define XS 132   // X  tile [128][128] A-operand   (S%32==4)
#define HS 68    // H  tile [128][64]  A-operand   (S%32==4)
#define WS1 72   // W1 tile [k=128][n=64] B-operand (S%32==8)
#define WS2 136  // W2 tile [k=64][n=128] B-operand (S%32==8)

#define SLOT_WORDS 9216          // max(128*72, 64*136)
#define OFF_X 0
#define OFF_H (128 * XS)                   // 16896
#define OFF_W (OFF_H + 128 * HS)           // 25600
#define SMEM_WORDS (OFF_W + 3 * SLOT_WORDS + 128)  // + stok
#define SMEM_BYTES (SMEM_WORDS * 4)

#define NW1 (NE * ND * NH)       // 1048576
#define NW2 (NE * NH * ND)       // 1048576

// ---------------- scratch ----------------
__device__ int g_counts[NE];
__device__ int g_bucket[NE * NB];
__device__ int g_sched_e[MAX_TILES];
__device__ int g_sched_base[MAX_TILES];
__device__ int g_ntiles;
__device__ int g_work;
__device__ float g_w1t[NW1];     // w1 pre-rounded to tf32 (RNA)
__device__ float g_w2t[NW2];     // w2 pre-rounded to tf32 (RNA)

// ---------------- helpers ----------------
__device__ __forceinline__ uint32_t smem_u32(const void* p) {
    uint32_t a;
    asm("{ .reg .u64 t; cvta.to.shared.u64 t, %1; cvt.u32.u64 %0, t; }" : "=r"(a) : "l"(p));
    return a;
}
__device__ __forceinline__ void cp16(uint32_t dst, const void* src) {
    asm volatile("cp.async.ca.shared.global [%0], [%1], 16;" :: "r"(dst), "l"(src));
}
#define CP_COMMIT() asm volatile("cp.async.commit_group;" ::: "memory")
#define CP_WAIT2()  asm volatile("cp.async.wait_group 2;" ::: "memory")

__device__ __forceinline__ uint32_t f2tf32(float f) {
    uint32_t r;
    asm("cvt.rna.tf32.f32 %0, %1;" : "=r"(r) : "f"(f));
    return r;
}
__device__ __forceinline__ float gelu_exact(float v) {
    return 0.5f * v * (1.0f + erff(v * 0.70710678118654752440f));
}
__device__ __forceinline__ void mma_tf32(float c[4], const uint32_t a[4], const uint32_t b[2]) {
    asm volatile(
        "mma.sync.aligned.m16n8k8.row.col.f32.tf32.tf32.f32 "
        "{%0,%1,%2,%3}, {%4,%5,%6,%7}, {%8,%9}, {%0,%1,%2,%3};\n"
        : "+f"(c[0]), "+f"(c[1]), "+f"(c[2]), "+f"(c[3])
        : "r"(a[0]), "r"(a[1]), "r"(a[2]), "r"(a[3]), "r"(b[0]), "r"(b[1]));
}

// Warp tile GEMM: 2 mtiles (m16) x NT ntiles (n8) x KS kslices (k8).
// Both operands are pre-rounded tf32 values stored as fp32 in smem.
template <int KS, int NT, int AS, int BS>
__device__ __forceinline__ void gemm_warp(const float* __restrict__ A,
                                          const float* __restrict__ B,
                                          float C[2][4][4],
                                          int mrow, int nbase, int gid, int tig) {
#pragma unroll
    for (int ks = 0; ks < KS; ks++) {
        const int kk = ks * 8;
        uint32_t a[2][4];
#pragma unroll
        for (int mt = 0; mt < 2; mt++) {
            const float* ap = A + (mrow + mt * 16 + gid) * AS + kk + tig;
            a[mt][0] = __float_as_uint(ap[0]);
            a[mt][1] = __float_as_uint(ap[8 * AS]);
            a[mt][2] = __float_as_uint(ap[4]);
            a[mt][3] = __float_as_uint(ap[8 * AS + 4]);
        }
        uint32_t bf[NT][2];
#pragma unroll
        for (int nt = 0; nt < NT; nt++) {
            const float* bp = B + (kk + tig) * BS + nbase + nt * 8 + gid;
            bf[nt][0] = __float_as_uint(bp[0]);
            bf[nt][1] = __float_as_uint(bp[4 * BS]);
        }
#pragma unroll
        for (int mt = 0; mt < 2; mt++)
#pragma unroll
            for (int nt = 0; nt < NT; nt++)
                mma_tf32(C[mt][nt], a[mt], bf[nt]);
    }
}

// ---------------------------------------------------------------------------
__global__ void zero_counts_kernel() {
    if (threadIdx.x < NE) g_counts[threadIdx.x] = 0;
}

// Pre-round weights to tf32 (RNA) once; removes per-fragment cvt from the
// GEMM inner loop (identical numerics, hoisted rounding).
__global__ void wconv_kernel(const float* __restrict__ w1,
                             const float* __restrict__ w2) {
    int i = blockIdx.x * blockDim.x + threadIdx.x;
    int n4 = NW1 / 4;
    for (; i < n4; i += gridDim.x * blockDim.x) {
        float4 a = ((const float4*)w1)[i];
        uint4 ta;
        ta.x = f2tf32(a.x); ta.y = f2tf32(a.y); ta.z = f2tf32(a.z); ta.w = f2tf32(a.w);
        ((uint4*)g_w1t)[i] = ta;
        float4 b = ((const float4*)w2)[i];
        uint4 tb;
        tb.x = f2tf32(b.x); tb.y = f2tf32(b.y); tb.z = f2tf32(b.z); tb.w = f2tf32(b.w);
        ((uint4*)g_w2t)[i] = tb;
    }
}

__global__ void route_kernel(const float* __restrict__ x,
                             const float* __restrict__ wg,
                             const float* __restrict__ bg) {
    __shared__ float swg[ND * NE];
    __shared__ float sbg[NE];
    for (int i = threadIdx.x; i < ND * NE; i += blockDim.x) swg[i] = wg[i];
    if (threadIdx.x < NE) sbg[threadIdx.x] = bg[threadIdx.x];
    __syncthreads();

    int b = blockIdx.x * blockDim.x + threadIdx.x;
    if (b >= NB) return;
    const float* xr = x + (size_t)b * ND;

    float acc[NE];
#pragma unroll
    for (int e = 0; e < NE; e++) acc[e] = sbg[e];
#pragma unroll 4
    for (int d = 0; d < ND; d++) {
        float xv = __ldg(xr + d);
#pragma unroll
        for (int e = 0; e < NE; e++) acc[e] = fmaf(xv, swg[d * NE + e], acc[e]);
    }
    float best = acc[0]; int bi = 0;
#pragma unroll
    for (int e = 1; e < NE; e++)
        if (acc[e] > best) { best = acc[e]; bi = e; }
    int pos = atomicAdd(&g_counts[bi], 1);
    g_bucket[bi * NB + pos] = b;
}

// Build flat tile schedule: one (expert, base) item per 128-token tile.
__global__ void sched_kernel() {
    if (threadIdx.x == 0) {
        int nt = 0;
#pragma unroll
        for (int e = 0; e < NE; e++) {
            int tiles = (g_counts[e] + 127) >> 7;
            for (int t = 0; t < tiles; t++) {
                g_sched_e[nt] = e;
                g_sched_base[nt] = t * 128;
                nt++;
            }
        }
        g_ntiles = nt;
        g_work = 0;
    }
}

// ---------------------------------------------------------------------------
// Persistent expert kernel: work-stealing blocks, 512 threads, 16 warps as
// 4(m) x 4(n). cp.async 3-slot ring pipelines tf32 weight chunks vs MMA.
// ---------------------------------------------------------------------------
__global__ __launch_bounds__(NTHREADS, 1)
void expert_gemm_pipe(const float* __restrict__ x,
                      float* __restrict__ out) {
    extern __shared__ __align__(128) float smem[];

    const uint32_t sb = smem_u32(smem);
    const int tid = threadIdx.x;
    const int lane = tid & 31;
    const int warp = tid >> 5;
    const int mg = warp & 3;          // m-group: rows [mg*32, +32)
    const int ng = warp >> 2;         // n-group (0..3)
    const int mrow = mg * 32;
    const int gid = lane >> 2;
    const int tig = lane & 3;
    int* stok = (int*)(smem + OFF_W + 3 * SLOT_WORDS);
    __shared__ int s_tile;

    const int ntiles = g_ntiles;

    for (;;) {
        if (tid == 0) s_tile = atomicAdd(&g_work, 1);
        __syncthreads();
        const int t = s_tile;
        if (t >= ntiles) break;

        const int e = g_sched_e[t];
        const int base = g_sched_base[t];
        const int count = g_counts[e];
        const float* w1e = g_w1t + (size_t)e * ND * NH;
        const float* w2e = g_w2t + (size_t)e * NH * ND;

        // ---- prologue: issue first 3 weight-chunk loads (stages 0,1,2) ----
        {
            uint32_t wbase = sb + (OFF_W + 0 * SLOT_WORDS) * 4;
#pragma unroll
            for (int i = 0; i < 4; i++) {
                int tt = tid + i * NTHREADS;       // 2048 16B segments
                int d = tt >> 4, c4 = (tt & 15) * 4;
                cp16(wbase + (d * WS1 + c4) * 4, w1e + (size_t)d * NH + 0 * CHUNK + c4);
            }
            CP_COMMIT();
            wbase = sb + (OFF_W + 1 * SLOT_WORDS) * 4;
#pragma unroll
            for (int i = 0; i < 4; i++) {
                int tt = tid + i * NTHREADS;
                int h = tt >> 5, c4 = (tt & 31) * 4;
                cp16(wbase + (h * WS2 + c4) * 4, w2e + (size_t)(0 * CHUNK + h) * ND + c4);
            }
            CP_COMMIT();
            wbase = sb + (OFF_W + 2 * SLOT_WORDS) * 4;
#pragma unroll
            for (int i = 0; i < 4; i++) {
                int tt = tid + i * NTHREADS;
                int d = tt >> 4, c4 = (tt & 15) * 4;
                cp16(wbase + (d * WS1 + c4) * 4, w1e + (size_t)d * NH + 1 * CHUNK + c4);
            }
            CP_COMMIT();
        }

        // ---- X tile: gathered token rows -> tf32(RNA) (overlaps cp.async) ----
        {
            int row = tid >> 2;
            int q = (tid & 3) * 32;
            int gi = base + row;
            int tok = (gi < count) ? g_bucket[e * NB + gi] : -1;
            if ((tid & 3) == 0) stok[row] = tok;
            float* dst = smem + OFF_X + row * XS + q;
            if (tok >= 0) {
                const float4* src = (const float4*)(x + (size_t)tok * ND + q);
#pragma unroll
                for (int j = 0; j < 8; j++) {
                    float4 v = src[j];
                    dst[j * 4 + 0] = __uint_as_float(f2tf32(v.x));
                    dst[j * 4 + 1] = __uint_as_float(f2tf32(v.y));
                    dst[j * 4 + 2] = __uint_as_float(f2tf32(v.z));
                    dst[j * 4 + 3] = __uint_as_float(f2tf32(v.w));
                }
            } else {
#pragma unroll
                for (int j = 0; j < 32; j++) dst[j] = 0.0f;
            }
        }
        __syncthreads();   // X + stok visible before first GEMM1

        float c2[2][4][4];
#pragma unroll
        for (int mt = 0; mt < 2; mt++)
#pragma unroll
            for (int nt = 0; nt < 4; nt++)
#pragma unroll
                for (int q = 0; q < 4; q++) c2[mt][nt][q] = 0.0f;

#pragma unroll 1
        for (int s = 0; s < NSTAGES; s++) {
            CP_WAIT2();          // group for stage s complete (<=2 younger pending)
            __syncthreads();

            const float* W = smem + OFF_W + (s % 3) * SLOT_WORDS;

            if ((s & 1) == 0) {
                // ---- GEMM1: c1 = X @ W1c  (M128 x N64 x K128), gelu -> H ----
                // warp n-tile: 16 cols at ng*16
                float c1[2][4][4];
#pragma unroll
                for (int mt = 0; mt < 2; mt++)
#pragma unroll
                    for (int nt = 0; nt < 2; nt++)
#pragma unroll
                        for (int q = 0; q < 4; q++) c1[mt][nt][q] = 0.0f;

                gemm_warp<16, 2, XS, WS1>(smem + OFF_X, W, c1, mrow, ng * 16, gid, tig);

#pragma unroll
                for (int mt = 0; mt < 2; mt++) {
                    int r0 = mrow + mt * 16 + gid;
#pragma unroll
                    for (int nt = 0; nt < 2; nt++) {
                        int col = ng * 16 + nt * 8 + tig * 2;
                        float* h0 = smem + OFF_H + r0 * HS + col;
                        float* h1 = smem + OFF_H + (r0 + 8) * HS + col;
                        h0[0] = __uint_as_float(f2tf32(gelu_exact(c1[mt][nt][0])));
                        h0[1] = __uint_as_float(f2tf32(gelu_exact(c1[mt][nt][1])));
                        h1[0] = __uint_as_float(f2tf32(gelu_exact(c1[mt][nt][2])));
                        h1[1] = __uint_as_float(f2tf32(gelu_exact(c1[mt][nt][3])));
                    }
                }
            } else {
                // ---- GEMM2: c2 += H @ W2c  (M128 x N128 x K64) ----
                // warp n-tile: 32 cols at ng*32
                gemm_warp<8, 4, HS, WS2>(smem + OFF_H, W, c2, mrow, ng * 32, gid, tig);
            }
            __syncthreads();     // slot s%3 + H free for reuse

            // ---- issue load for stage s+3 into the slot just freed ----
            int ns = s + 3;
            if (ns < NSTAGES) {
                uint32_t wbase = sb + (OFF_W + (ns % 3) * SLOT_WORDS) * 4;
                int hc = ns >> 1;
                if ((ns & 1) == 0) {
#pragma unroll
                    for (int i = 0; i < 4; i++) {
                        int tt = tid + i * NTHREADS;
                        int d = tt >> 4, c4 = (tt & 15) * 4;
                        cp16(wbase + (d * WS1 + c4) * 4, w1e + (size_t)d * NH + hc * CHUNK + c4);
                    }
                } else {
#pragma unroll
                    for (int i = 0; i < 4; i++) {
                        int tt = tid + i * NTHREADS;
                        int h = tt >> 5, c4 = (tt & 31) * 4;
                        cp16(wbase + (h * WS2 + c4) * 4, w2e + (size_t)(hc * CHUNK + h) * ND + c4);
                    }
                }
            }
            CP_COMMIT();         // empty groups in the tail keep wait_group 2 exact
        }

        // ---- epilogue: c2 -> out[token] (top-1 softmax score == 1.0) ----
#pragma unroll
        for (int mt = 0; mt < 2; mt++) {
            int r0 = mrow + mt * 16 + gid;
#pragma unroll
            for (int half = 0; half < 2; half++) {
                int r = r0 + half * 8;
                int tok = stok[r];
                if (tok >= 0) {
                    float* o = out + (size_t)tok * ND;
#pragma unroll
                    for (int nt = 0; nt < 4; nt++) {
                        int col = ng * 32 + nt * 8 + tig * 2;
                        float2 v = make_float2(c2[mt][nt][2 * half], c2[mt][nt][2 * half + 1]);
                        *(float2*)(o + col) = v;
                    }
                }
            }
        }
        __syncthreads();   // stok/smem safe to reuse in next work item
    }
}

// ---------------------------------------------------------------------------
extern "C" void kernel_launch(void* const* d_in, const int* in_sizes, int n_in,
                              void* d_out, int out_size) {
    const float* x  = (const float*)d_in[0];
    const float* w1 = (const float*)d_in[1];
    const float* w2 = (const float*)d_in[2];
    const float* wg = (const float*)d_in[3];
    const float* bg = (const float*)d_in[4];
    float* out = (float*)d_out;

    zero_counts_kernel<<<1, 32>>>();
    wconv_kernel<<<512, 256>>>(w1, w2);
    route_kernel<<<NB / 256, 256>>>(x, wg, bg);
    sched_kernel<<<1, 32>>>();

    cudaFuncSetAttribute(expert_gemm_pipe,
                         cudaFuncAttributeMaxDynamicSharedMemorySize, SMEM_BYTES);
    expert_gemm_pipe<<<NBLOCKS, NTHREADS, SMEM_BYTES>>>(x, out);
}

// round 16
// speedup vs baseline: 1.0660x; 1.0660x over previous
#include <cuda_runtime.h>
#include <math.h>
#include <cstdint>

#define NB 32768
#define ND 128
#define NH 512
#define NE 16
#define CHUNK 64
#define NCHUNKS (NH / CHUNK)     // 8
#define NSTAGES (NCHUNKS * 2)    // 16: G1/G2 alternating
#define MAX_TILES 320
#define NBLOCKS 256
#define NTHREADS 256             // 8 warps: 4(m) x 2(n)

#define SLOT_WORDS 8192          // dense packed chunk: 32 KB (both G1 and G2)
#define OFF_X 0                  // X packed: 16384 words (64 KB)
#define OFF_H 16384              // H packed: 8192 words (32 KB)
#define OFF_W 24576              // 3 slots x 8192
#define SMEM_WORDS (OFF_W + 3 * SLOT_WORDS + 128)
#define SMEM_BYTES (SMEM_WORDS * 4)

#define NW1 (NE * ND * NH)
#define NW2 (NE * NH * ND)

// ---------------- scratch ----------------
__device__ int g_counts[NE];
__device__ int g_bucket[NE * NB];
__device__ int g_sched_e[MAX_TILES];
__device__ int g_sched_base[MAX_TILES];
__device__ int g_ntiles;
__device__ int g_work;
__device__ float g_w1p[NW1];     // w1 tf32, frag-pair packed per (expert, chunk)
__device__ float g_w2p[NW2];     // w2 tf32, frag-pair packed per (expert, chunk)

// ---------------- helpers ----------------
__device__ __forceinline__ uint32_t smem_u32(const void* p) {
    uint32_t a;
    asm("{ .reg .u64 t; cvta.to.shared.u64 t, %1; cvt.u32.u64 %0, t; }" : "=r"(a) : "l"(p));
    return a;
}
__device__ __forceinline__ void cp16(uint32_t dst, const void* src) {
    asm volatile("cp.async.ca.shared.global [%0], [%1], 16;" :: "r"(dst), "l"(src));
}
#define CP_COMMIT() asm volatile("cp.async.commit_group;" ::: "memory")
#define CP_WAIT2()  asm volatile("cp.async.wait_group 2;" ::: "memory")

__device__ __forceinline__ uint32_t f2tf32(float f) {
    uint32_t r;
    asm("cvt.rna.tf32.f32 %0, %1;" : "=r"(r) : "f"(f));
    return r;
}
__device__ __forceinline__ float gelu_exact(float v) {
    return 0.5f * v * (1.0f + erff(v * 0.70710678118654752440f));
}
__device__ __forceinline__ void mma_tf32(float c[4], const uint32_t a[4], const uint32_t b[2]) {
    asm volatile(
        "mma.sync.aligned.m16n8k8.row.col.f32.tf32.tf32.f32 "
        "{%0,%1,%2,%3}, {%4,%5,%6,%7}, {%8,%9}, {%0,%1,%2,%3};\n"
        : "+f"(c[0]), "+f"(c[1]), "+f"(c[2]), "+f"(c[3])
        : "r"(a[0]), "r"(a[1]), "r"(a[2]), "r"(a[3]), "r"(b[0]), "r"(b[1]));
}

// Packed-layout warp GEMM.
// A packed: float4[(m16*KS + ks)*8 + r][t'] holding regs (r,k),(r+8,k),(r,k+4),(r+8,k+4),
//           t' = (t + r) & 3 rotation (conflict-free reads). One LDS.128 per frag.
// B packed: float2[(ks*NC + n)*4 + t] holding (k,n),(k+4,n). One LDS.64 per frag.
template <int KS, int NT, int NC>
__device__ __forceinline__ void gemm_packed(const float* __restrict__ A,
                                            const float* __restrict__ B,
                                            float C[2][NT][4],
                                            int m16b, int nbase, int gid, int tig) {
    const float4* Ap = (const float4*)A;
    const float2* Bp = (const float2*)B;
    const int tr = (tig + gid) & 3;
#pragma unroll
    for (int ks = 0; ks < KS; ks++) {
        float4 av[2];
#pragma unroll
        for (int mt = 0; mt < 2; mt++)
            av[mt] = Ap[(((m16b + mt) * KS + ks) * 8 + gid) * 4 + tr];
        float2 bv[NT];
#pragma unroll
        for (int nt = 0; nt < NT; nt++)
            bv[nt] = Bp[(ks * NC + nbase + nt * 8 + gid) * 4 + tig];
#pragma unroll
        for (int mt = 0; mt < 2; mt++) {
            uint32_t a[4] = {__float_as_uint(av[mt].x), __float_as_uint(av[mt].y),
                             __float_as_uint(av[mt].z), __float_as_uint(av[mt].w)};
#pragma unroll
            for (int nt = 0; nt < NT; nt++) {
                uint32_t b[2] = {__float_as_uint(bv[nt].x), __float_as_uint(bv[nt].y)};
                mma_tf32(C[mt][nt], a, b);
            }
        }
    }
}

// ---------------------------------------------------------------------------
// prep: zero counts + convert/pack weights to tf32 frag-pair layout.
// w1 [e][d][h]: GEMM1 B (k=d, n=h within 64-chunk).
// w2 [e][h][d]: GEMM2 B (k=h within 64-chunk, n=d).
// ---------------------------------------------------------------------------
__global__ void prep_kernel(const float* __restrict__ w1,
                            const float* __restrict__ w2) {
    int i0 = blockIdx.x * blockDim.x + threadIdx.x;
    if (i0 < NE) g_counts[i0] = 0;
    for (int i = i0; i < NW1; i += gridDim.x * blockDim.x) {
        int e = i >> 16;            // ND*NH = 65536
        int rem = i & 65535;
        // ---- w1 ----
        {
            int d = rem >> 9;       // NH = 512
            int h = rem & 511;
            int hc = h >> 6, n = h & 63;
            int ks = d >> 3, kr = d & 7, t = kr & 3, khi = kr >> 2;
            int idx = ((((e * 8 + hc) * 16 + ks) * 64 + n) * 4 + t) * 2 + khi;
            g_w1p[idx] = __uint_as_float(f2tf32(w1[i]));
        }
        // ---- w2 ----
        {
            int h = rem >> 7;       // ND = 128
            int d = rem & 127;
            int hc = h >> 6, hl = h & 63;
            int ks = hl >> 3, kr = hl & 7, t = kr & 3, khi = kr >> 2;
            int idx = ((((e * 8 + hc) * 8 + ks) * 128 + d) * 4 + t) * 2 + khi;
            g_w2p[idx] = __uint_as_float(f2tf32(w2[i]));
        }
    }
}

__global__ void route_kernel(const float* __restrict__ x,
                             const float* __restrict__ wg,
                             const float* __restrict__ bg) {
    __shared__ float swg[ND * NE];
    __shared__ float sbg[NE];
    for (int i = threadIdx.x; i < ND * NE; i += blockDim.x) swg[i] = wg[i];
    if (threadIdx.x < NE) sbg[threadIdx.x] = bg[threadIdx.x];
    __syncthreads();

    int b = blockIdx.x * blockDim.x + threadIdx.x;
    if (b >= NB) return;
    const float* xr = x + (size_t)b * ND;

    float acc[NE];
#pragma unroll
    for (int e = 0; e < NE; e++) acc[e] = sbg[e];
#pragma unroll 4
    for (int d = 0; d < ND; d++) {
        float xv = __ldg(xr + d);
#pragma unroll
        for (int e = 0; e < NE; e++) acc[e] = fmaf(xv, swg[d * NE + e], acc[e]);
    }
    float best = acc[0]; int bi = 0;
#pragma unroll
    for (int e = 1; e < NE; e++)
        if (acc[e] > best) { best = acc[e]; bi = e; }
    int pos = atomicAdd(&g_counts[bi], 1);
    g_bucket[bi * NB + pos] = b;
}

// Parallel tile schedule: warp scan over per-expert tile counts.
__global__ void sched_kernel() {
    int e = threadIdx.x;
    int tiles = (e < NE) ? ((g_counts[e] + 127) >> 7) : 0;
    int inc = tiles;
#pragma unroll
    for (int d = 1; d < 32; d <<= 1) {
        int v = __shfl_up_sync(0xFFFFFFFFu, inc, d);
        if (threadIdx.x >= d) inc += v;
    }
    int off = inc - tiles;   // exclusive prefix
    if (e < NE)
        for (int t = 0; t < tiles; t++) {
            g_sched_e[off + t] = e;
            g_sched_base[off + t] = t * 128;
        }
    if (threadIdx.x == 31) { g_ntiles = inc; g_work = 0; }
}

// ---------------------------------------------------------------------------
// Persistent expert kernel: work-stealing, 256 threads, 8 warps 4(m)x2(n).
// Per h-chunk (64): G1 c1 = X@W1c (K=128,N=64) -> gelu -> packed H;
//                   G2 c2 += H@W2c (K=64,N=128). cp.async 3-slot ring.
// ---------------------------------------------------------------------------
__global__ __launch_bounds__(NTHREADS, 1)
void expert_gemm_pipe(const float* __restrict__ x,
                      float* __restrict__ out) {
    extern __shared__ __align__(128) float smem[];

    const uint32_t sb = smem_u32(smem);
    const int tid = threadIdx.x;
    const int lane = tid & 31;
    const int warp = tid >> 5;
    const int mg = warp & 3;          // m-group: rows [mg*32, +32)
    const int ng = warp >> 2;         // n-group (0..1)
    const int gid = lane >> 2;
    const int tig = lane & 3;
    float* Xp = smem + OFF_X;
    float* Hp = smem + OFF_H;
    int* stok = (int*)(smem + OFF_W + 3 * SLOT_WORDS);
    __shared__ int s_tile;

    const int ntiles = g_ntiles;

    for (;;) {
        if (tid == 0) s_tile = atomicAdd(&g_work, 1);
        __syncthreads();
        const int t = s_tile;
        if (t >= ntiles) break;

        const int e = g_sched_e[t];
        const int base = g_sched_base[t];
        const int count = g_counts[e];
        const float* w1e = g_w1p + (size_t)e * 8 * SLOT_WORDS;
        const float* w2e = g_w2p + (size_t)e * 8 * SLOT_WORDS;

        // ---- prologue: stage 0 (W1 hc0), 1 (W2 hc0), 2 (W1 hc1) ----
#pragma unroll
        for (int ps = 0; ps < 3; ps++) {
            uint32_t wb = sb + (OFF_W + ps * SLOT_WORDS) * 4;
            const float* src = (ps == 1) ? (w2e + 0 * SLOT_WORDS)
                                         : (w1e + (size_t)(ps >> 1) * SLOT_WORDS);
#pragma unroll
            for (int i = 0; i < 8; i++) {
                int tt = tid + i * NTHREADS;       // 2048 float4 segments
                cp16(wb + tt * 16, src + tt * 4);
            }
            CP_COMMIT();
        }

        // ---- X tile gather -> tf32, frag-packed (overlaps cp.async) ----
        {
            int row = tid >> 1;
            int half = (tid & 1) * 64;
            int gi = base + row;
            int tok = (gi < count) ? g_bucket[e * NB + gi] : -1;
            if ((tid & 1) == 0) stok[row] = tok;
            int m16 = row >> 4, r7 = row & 7, hi = (row >> 3) & 1;
            if (tok >= 0) {
                const float4* src = (const float4*)(x + (size_t)tok * ND + half);
#pragma unroll
                for (int g = 0; g < 8; g++) {
                    int ks = (half >> 3) + g;
                    float4 v0 = src[g * 2], v1 = src[g * 2 + 1];
                    float vals[8] = {v0.x, v0.y, v0.z, v0.w, v1.x, v1.y, v1.z, v1.w};
                    int wb = ((m16 * 16 + ks) * 8 + r7) * 16 + hi;
#pragma unroll
                    for (int kk = 0; kk < 8; kk++) {
                        int tp = ((kk & 3) + r7) & 3;
                        Xp[wb + tp * 4 + (kk >> 2) * 2] =
                            __uint_as_float(f2tf32(vals[kk]));
                    }
                }
            } else {
#pragma unroll
                for (int g = 0; g < 8; g++) {
                    int ks = (half >> 3) + g;
                    int wb = ((m16 * 16 + ks) * 8 + r7) * 16 + hi;
#pragma unroll
                    for (int kk = 0; kk < 8; kk++) {
                        int tp = ((kk & 3) + r7) & 3;
                        Xp[wb + tp * 4 + (kk >> 2) * 2] = 0.0f;
                    }
                }
            }
        }
        __syncthreads();   // X + stok visible before first GEMM1

        float c2[2][8][4];
#pragma unroll
        for (int mt = 0; mt < 2; mt++)
#pragma unroll
            for (int nt = 0; nt < 8; nt++)
#pragma unroll
                for (int q = 0; q < 4; q++) c2[mt][nt][q] = 0.0f;

#pragma unroll 1
        for (int s = 0; s < NSTAGES; s++) {
            CP_WAIT2();
            __syncthreads();

            const float* W = smem + OFF_W + (s % 3) * SLOT_WORDS;

            if ((s & 1) == 0) {
                // ---- GEMM1 + gelu -> packed H ----
                float c1[2][4][4];
#pragma unroll
                for (int mt = 0; mt < 2; mt++)
#pragma unroll
                    for (int nt = 0; nt < 4; nt++)
#pragma unroll
                        for (int q = 0; q < 4; q++) c1[mt][nt][q] = 0.0f;

                gemm_packed<16, 4, 64>(Xp, W, c1, mg * 2, ng * 32, gid, tig);

#pragma unroll
                for (int mt = 0; mt < 2; mt++) {
                    int m16 = mg * 2 + mt;
#pragma unroll
                    for (int nt = 0; nt < 4; nt++) {
                        int ks = ng * 4 + nt;              // h-col group -> G2 k-slice
                        int wb = ((m16 * 8 + ks) * 8 + gid) * 16;
#pragma unroll
                        for (int q = 0; q < 4; q++) {
                            int k7 = tig * 2 + (q & 1);
                            int tp = ((k7 & 3) + gid) & 3;
                            int slot = (k7 >> 2) * 2 + (q >> 1);
                            Hp[wb + tp * 4 + slot] =
                                __uint_as_float(f2tf32(gelu_exact(c1[mt][nt][q])));
                        }
                    }
                }
            } else {
                // ---- GEMM2: c2 += H @ W2c ----
                gemm_packed<8, 8, 128>(Hp, W, c2, mg * 2, ng * 64, gid, tig);
            }
            __syncthreads();     // slot s%3 + H free for reuse

            // ---- load stage s+3 into freed slot ----
            int ns = s + 3;
            if (ns < NSTAGES) {
                uint32_t wb = sb + (OFF_W + (ns % 3) * SLOT_WORDS) * 4;
                int hc = ns >> 1;
                const float* src = ((ns & 1) ? w2e : w1e) + (size_t)hc * SLOT_WORDS;
#pragma unroll
                for (int i = 0; i < 8; i++) {
                    int tt = tid + i * NTHREADS;
                    cp16(wb + tt * 16, src + tt * 4);
                }
            }
            CP_COMMIT();
        }

        // ---- epilogue: c2 -> out[token] (top-1 softmax score == 1.0) ----
#pragma unroll
        for (int mt = 0; mt < 2; mt++) {
            int r0 = mg * 32 + mt * 16 + gid;
#pragma unroll
            for (int half = 0; half < 2; half++) {
                int r = r0 + half * 8;
                int tok = stok[r];
                if (tok >= 0) {
                    float* o = out + (size_t)tok * ND;
#pragma unroll
                    for (int nt = 0; nt < 8; nt++) {
                        int col = ng * 64 + nt * 8 + tig * 2;
                        float2 v = make_float2(c2[mt][nt][2 * half], c2[mt][nt][2 * half + 1]);
                        *(float2*)(o + col) = v;
                    }
                }
            }
        }
        __syncthreads();   // smem safe to reuse in next work item
    }
}

// ---------------------------------------------------------------------------
extern "C" void kernel_launch(void* const* d_in, const int* in_sizes, int n_in,
                              void* d_out, int out_size) {
    const float* x  = (const float*)d_in[0];
    const float* w1 = (const float*)d_in[1];
    const float* w2 = (const float*)d_in[2];
    const float* wg = (const float*)d_in[3];
    const float* bg = (const float*)d_in[4];
    float* out = (float*)d_out;

    prep_kernel<<<512, 256>>>(w1, w2);
    route_kernel<<<NB / 256, 256>>>(x, wg, bg);
    sched_kernel<<<1, 32>>>();

    cudaFuncSetAttribute(expert_gemm_pipe,
                         cudaFuncAttributeMaxDynamicSharedMemorySize, SMEM_BYTES);
    expert_gemm_pipe<<<NBLOCKS, NTHREADS, SMEM_BYTES>>>(x, out);
}